// round 16
// baseline (speedup 1.0000x reference)
#include <cuda_runtime.h>

// out = noised + 0.1f * noise   (elementwise, N = 50,331,648 fp32)
// Hybrid-width experiment: 128-bit loads (measured-best read width,
// preserves request-level parallelism: 4 independent LDG.128/thread)
// + one 256-bit evict-first store per 8 elements (halves STG count;
// stores are fire-and-forget so wider is free on the write path).

__device__ __forceinline__ void st_256_cs(float* __restrict__ p, const float r[8]) {
    asm volatile(
        "st.global.cs.v8.f32 [%0], {%1,%2,%3,%4,%5,%6,%7,%8};"
        :
        : "l"(p),
          "f"(r[0]), "f"(r[1]), "f"(r[2]), "f"(r[3]),
          "f"(r[4]), "f"(r[5]), "f"(r[6]), "f"(r[7])
        : "memory");
}

__global__ void __launch_bounds__(256) gaussian_noise_axpy_hybrid(
    const float4* __restrict__ noised,
    const float4* __restrict__ noise,
    float* __restrict__ out,
    int n8)   // number of 8-element groups
{
    int i = blockIdx.x * blockDim.x + threadIdx.x;
    if (i < n8) {
        // 4 independent 128-bit loads (2 per input array).
        float4 a0 = noised[2 * i];
        float4 a1 = noised[2 * i + 1];
        float4 b0 = noise [2 * i];
        float4 b1 = noise [2 * i + 1];

        float r[8];
        r[0] = fmaf(0.1f, b0.x, a0.x);
        r[1] = fmaf(0.1f, b0.y, a0.y);
        r[2] = fmaf(0.1f, b0.z, a0.z);
        r[3] = fmaf(0.1f, b0.w, a0.w);
        r[4] = fmaf(0.1f, b1.x, a1.x);
        r[5] = fmaf(0.1f, b1.y, a1.y);
        r[6] = fmaf(0.1f, b1.z, a1.z);
        r[7] = fmaf(0.1f, b1.w, a1.w);

        st_256_cs(out + (size_t)i * 8, r);
    }
}

// Scalar tail fallback (not expected to trigger for this shape, but keeps the
// kernel correct for any element count).
__global__ void gaussian_noise_axpy_tail(
    const float* __restrict__ noised,
    const float* __restrict__ noise,
    float* __restrict__ out,
    int start, int n)
{
    int i = start + blockIdx.x * blockDim.x + threadIdx.x;
    if (i < n) {
        out[i] = fmaf(0.1f, noise[i], noised[i]);
    }
}

extern "C" void kernel_launch(void* const* d_in, const int* in_sizes, int n_in,
                              void* d_out, int out_size)
{
    const float* noised = (const float*)d_in[0];
    const float* noise  = (const float*)d_in[1];
    float* out = (float*)d_out;
    int n = in_sizes[0];

    int n8 = n >> 3;   // 8 elements per thread
    if (n8 > 0) {
        const int threads = 256;
        int blocks = (n8 + threads - 1) / threads;
        gaussian_noise_axpy_hybrid<<<blocks, threads>>>(
            (const float4*)noised, (const float4*)noise, out, n8);
    }
    int done = n8 << 3;
    if (done < n) {
        int rem = n - done;
        gaussian_noise_axpy_tail<<<(rem + 255) / 256, 256>>>(noised, noise, out, done, n);
    }
}